// round 16
// baseline (speedup 1.0000x reference)
#include <cuda_runtime.h>
#include <cuda_bf16.h>
#include <cuda_fp16.h>
#include <math.h>

// ---------------------------------------------------------------------------
// QuantumAttention, analytic circuit collapse:
//   z_i = cos(x_i + p_i); proj[0] = z1..z7 ; proj[w>=1] = z0..zw
// qkv_pack: projections -> K/V in FRAGMENT-ORDER f16 layouts. attn: QK
// m16n8k8 f16-accum -> packed C-regs ARE PV A-frags; ex2.approx.f16x2 in
// place. Softmax denominators on the FMA pipe (HADD2 + cvt) instead of
// ones-mma: tensor work/iter drops 12 -> 8 m16n8k8-equiv. Split-K 4,
// unnormalized partials. combine: split-tf32 GEMM + fused reduction/norm.
// ---------------------------------------------------------------------------

#define NROWS   65536
#define S_LEN   1024
#define NHEADS  64
#define DK      8
#define E_DIM   128
#define NROWS_E 4096
#define NSPLIT  4
#define KS_LEN  256          // keys per split block

__device__ float g_po[NSPLIT * NROWS_E * E_DIM];   // unnormalized O partials (8 MB)
__device__ float g_pl[NSPLIT * NROWS_E * 16];      // denominator partials (1 MB)
__device__ uint4 g_wb[16 * 16 * 32];               // W split B-fragments
__device__ unsigned g_k2[NHEADS * 4096];           // K f16x2, fragment order (1 MB)
__device__ unsigned g_v2[NHEADS * 4096];           // V f16x2, fragment order (1 MB)

__device__ __forceinline__ unsigned tf32_of(float f) {
    unsigned u; asm("cvt.rna.tf32.f32 %0, %1;" : "=r"(u) : "f"(f));
    return u;
}
__device__ __forceinline__ unsigned h2_of(float lo, float hi) {
    __half2 h = __floats2half2_rn(lo, hi);
    return *reinterpret_cast<unsigned*>(&h);
}
// forced single-instruction packed exp2
__device__ __forceinline__ unsigned ex2_h2(unsigned s) {
    unsigned d;
    asm("ex2.approx.f16x2 %0, %1;" : "=r"(d) : "r"(s));
    return d;
}
__device__ __forceinline__ unsigned hadd2u(unsigned a, unsigned b) {
    unsigned d;
    asm("add.f16x2 %0, %1, %2;" : "=r"(d) : "r"(a), "r"(b));
    return d;
}
__device__ __forceinline__ float2 h22f2(unsigned h) {
    __half2 hh = *reinterpret_cast<__half2*>(&h);
    return __half22float2(hh);
}
// f16 m16n8k8 with F16 accumulator: C packed as 2 f16x2 regs
//   c01 = {row g  : keys 2t4, 2t4+1}, c23 = {row g+8: same}
__device__ __forceinline__ void mma8hh(unsigned& c01, unsigned& c23,
                                       unsigned a0, unsigned a1, unsigned b0) {
    asm("mma.sync.aligned.m16n8k8.row.col.f16.f16.f16.f16 "
        "{%0,%1},{%2,%3},{%4},{%5,%6};"
        : "=r"(c01), "=r"(c23)
        : "r"(a0), "r"(a1), "r"(b0), "r"(0u), "r"(0u));
}
// f16 m16n8k16, C(f32) += A*B
__device__ __forceinline__ void mma16h_acc(float& c0, float& c1, float& c2, float& c3,
                                           unsigned a0, unsigned a1, unsigned a2, unsigned a3,
                                           unsigned b0, unsigned b1) {
    asm("mma.sync.aligned.m16n8k16.row.col.f32.f16.f16.f32 "
        "{%0,%1,%2,%3},{%4,%5,%6,%7},{%8,%9},{%0,%1,%2,%3};"
        : "+f"(c0), "+f"(c1), "+f"(c2), "+f"(c3)
        : "r"(a0), "r"(a1), "r"(a2), "r"(a3), "r"(b0), "r"(b1));
}
// tf32 m16n8k8, C += A*B
__device__ __forceinline__ void mma8_acc(float& c0, float& c1, float& c2, float& c3,
                                         unsigned a0, unsigned a1, unsigned a2, unsigned a3,
                                         unsigned b0, unsigned b1) {
    asm("mma.sync.aligned.m16n8k8.row.col.f32.tf32.tf32.f32 "
        "{%0,%1,%2,%3},{%4,%5,%6,%7},{%8,%9},{%0,%1,%2,%3};"
        : "+f"(c0), "+f"(c1), "+f"(c2), "+f"(c3)
        : "r"(a0), "r"(a1), "r"(a2), "r"(a3), "r"(b0), "r"(b1));
}

__device__ __forceinline__ void proj8(float4 v0, float4 v1,
                                      const float* pv, float* o) {
    float z0 = __cosf(v0.x + pv[0]);
    float z1 = __cosf(v0.y + pv[1]);
    float z2 = __cosf(v0.z + pv[2]);
    float z3 = __cosf(v0.w + pv[3]);
    float z4 = __cosf(v1.x + pv[4]);
    float z5 = __cosf(v1.y + pv[5]);
    float z6 = __cosf(v1.z + pv[6]);
    float z7 = __cosf(v1.w + pv[7]);
    o[1] = z0 * z1;
    o[2] = o[1] * z2;
    o[3] = o[2] * z3;
    o[4] = o[3] * z4;
    o[5] = o[4] * z5;
    o[6] = o[5] * z6;
    o[7] = o[6] * z7;
    float t = z1 * z2;
    t *= z3; t *= z4; t *= z5; t *= z6; t *= z7;
    o[0] = t;
}

// fragment-order index for K word (row r, dim-slot t4) within a head
__device__ __forceinline__ int kidx(int r, int t4) {
    return (((r >> 5) * 8 + (r & 7)) << 4) + t4 * 4 + ((r & 31) >> 3);
}
// fragment-order index for V word (pair p, dim g)
__device__ __forceinline__ int vidx(int p, int g) {
    return (((p >> 4) * 8 + g) << 4) + (p & 3) * 4 + ((p & 15) >> 2);
}

__global__ void nop_kernel() {}

// ---------------------------------------------------------------------------
// Kernel 1: projection + fragment-order f16 packing.
// ---------------------------------------------------------------------------
__global__ void qkv_pack(const float* __restrict__ x,
                         const float* __restrict__ rx) {
    int r = blockIdx.x * blockDim.x + threadIdx.x;   // pair idx
    if (r >= NHEADS * (S_LEN / 2)) return;
    int head = r >> 9;
    int j = r & 511;
    int bb = head >> 4;
    int hh = head & 15;

    float pv[8];
#pragma unroll
    for (int i = 0; i < 8; i++) pv[i] = __ldg(rx + i);

    const float4* x4 = reinterpret_cast<const float4*>(x);
    size_t r0 = ((size_t)((bb << 10) + 2 * j) << 4) + hh;
    float4 a0 = x4[r0 * 2];
    float4 a1 = x4[r0 * 2 + 1];
    float4 c0 = x4[(r0 + 16) * 2];
    float4 c1 = x4[(r0 + 16) * 2 + 1];

    float o[8], p[8];
    proj8(a0, a1, pv, o);
    proj8(c0, c1, pv, p);

    const float rs = 0.71421915f;   // sqrt(log2e / sqrt(8))
    unsigned* K = g_k2 + head * 4096;
    unsigned* V = g_v2 + head * 4096;

#pragma unroll
    for (int t4 = 0; t4 < 4; t4++) {
        K[kidx(2 * j,     t4)] = h2_of(o[2 * t4] * rs, o[2 * t4 + 1] * rs);
        K[kidx(2 * j + 1, t4)] = h2_of(p[2 * t4] * rs, p[2 * t4 + 1] * rs);
    }
#pragma unroll
    for (int g = 0; g < 8; g++) {
        V[vidx(j, g)] = h2_of(o[g], p[g]);
    }
}

// ---------------------------------------------------------------------------
// Kernel 2: split-K(4) attention; denominators on the fma pipe.
// bx: head = bx>>5, qt = (bx>>2)&7, ks = bx&3. 256 thr; 128 q x 256 keys.
// ---------------------------------------------------------------------------
__global__ __launch_bounds__(256, 5) void attn_kernel() {
    __shared__ __align__(16) unsigned sK2[1024];   // 4 KB
    __shared__ __align__(16) unsigned sV2[1024];   // 4 KB

    int bx   = blockIdx.x;
    int head = bx >> 5;
    int qt   = (bx >> 2) & 7;
    int ks   = bx & 3;
    int tid  = threadIdx.x;
    int w    = tid >> 5;
    int lane = tid & 31;
    int g    = lane >> 2;
    int t4   = lane & 3;

    const uint4* Ksrc = reinterpret_cast<const uint4*>(g_k2 + head * 4096 + ks * 1024);
    const uint4* Vsrc = reinterpret_cast<const uint4*>(g_v2 + head * 4096 + ks * 1024);
    reinterpret_cast<uint4*>(sK2)[tid] = Ksrc[tid];
    reinterpret_cast<uint4*>(sV2)[tid] = Vsrc[tid];
    __syncthreads();

    // Q A-frag: rows ar, ar+8 -> one LDG.64 (adjacent in fragment order)
    int ar = qt * 128 + w * 16 + g;
    const unsigned* Kg = g_k2 + head * 4096;
    uint2 Aq = *reinterpret_cast<const uint2*>(Kg + kidx(ar, t4));
    unsigned A0 = Aq.x, A1 = Aq.y;

    float Oa0 = 0.f, Oa1 = 0.f, Oa2 = 0.f, Oa3 = 0.f;
    float Ob0 = 0.f, Ob1 = 0.f, Ob2 = 0.f, Ob3 = 0.f;
    float Lg = 0.f, Lg8 = 0.f;     // per-thread denominator partials (f32)

    int fo = g * 16 + t4 * 4;    // lane offset within a 128-word block

#pragma unroll
    for (int it = 0; it < KS_LEN / 32; it++) {
        uint4 kq = *reinterpret_cast<const uint4*>(sK2 + it * 128 + fo);
        uint4 vq = *reinterpret_cast<const uint4*>(sV2 + it * 128 + fo);

        // QK with f16 accumulators: packed C-regs ARE the PV A-frag pairs
        unsigned s0, s1, t0, t1, u0, u1, v0, v1;
        mma8hh(s0, s1, A0, A1, kq.x);    // keys it*32 +  0.. 7
        mma8hh(t0, t1, A0, A1, kq.y);    // keys it*32 +  8..15
        mma8hh(u0, u1, A0, A1, kq.z);    // keys it*32 + 16..23
        mma8hh(v0, v1, A0, A1, kq.w);    // keys it*32 + 24..31

        unsigned pa01 = ex2_h2(s0);
        unsigned pa23 = ex2_h2(s1);
        unsigned ea01 = ex2_h2(t0);
        unsigned ea23 = ex2_h2(t1);
        unsigned pb01 = ex2_h2(u0);
        unsigned pb23 = ex2_h2(u1);
        unsigned eb01 = ex2_h2(v0);
        unsigned eb23 = ex2_h2(v1);

        mma16h_acc(Oa0, Oa1, Oa2, Oa3, pa01, pa23, ea01, ea23, vq.x, vq.y);
        mma16h_acc(Ob0, Ob1, Ob2, Ob3, pb01, pb23, eb01, eb23, vq.z, vq.w);

        // denominators on the fma pipe: one f16 pair-add, then f32 accumulate
        unsigned sg0 = hadd2u(pa01, ea01);
        unsigned sg1 = hadd2u(pb01, eb01);
        unsigned s80 = hadd2u(pa23, ea23);
        unsigned s81 = hadd2u(pb23, eb23);
        float2 f0 = h22f2(sg0);
        float2 f1 = h22f2(sg1);
        float2 f2 = h22f2(s80);
        float2 f3 = h22f2(s81);
        Lg  += (f0.x + f0.y) + (f1.x + f1.y);
        Lg8 += (f2.x + f2.y) + (f3.x + f3.y);
    }

    float O0 = Oa0 + Ob0, O1 = Oa1 + Ob1, O2 = Oa2 + Ob2, O3 = Oa3 + Ob3;

    // reduce denominators across the 4 t4 lanes of each group
    Lg  += __shfl_xor_sync(0xffffffffu, Lg, 1);
    Lg  += __shfl_xor_sync(0xffffffffu, Lg, 2);
    Lg8 += __shfl_xor_sync(0xffffffffu, Lg8, 1);
    Lg8 += __shfl_xor_sync(0xffffffffu, Lg8, 2);

    int bb_ = head >> 4;
    int hh  = head & 15;
    int row = qt * 128 + w * 16 + g;
    int grow = (bb_ << 10) + row;
    size_t base = (size_t)ks * NROWS_E * E_DIM + (size_t)grow * E_DIM + hh * DK + 2 * t4;

    *reinterpret_cast<float2*>(g_po + base)              = make_float2(O0, O1);
    *reinterpret_cast<float2*>(g_po + base + 8 * E_DIM)  = make_float2(O2, O3);

    if (t4 == 0) {
        g_pl[ks * NROWS_E * 16 + grow * 16 + hh]       = Lg;
        g_pl[ks * NROWS_E * 16 + (grow + 8) * 16 + hh] = Lg8;
    }
}

// ---------------------------------------------------------------------------
// Kernel 3a: pack W into split B-fragments (hi/lo tf32).
// ---------------------------------------------------------------------------
__global__ void pack_w(const float* __restrict__ W) {
    int j = blockIdx.x * blockDim.x + threadIdx.x;
    if (j >= 16 * 16 * 32) return;
    int lane = j & 31;
    int et   = (j >> 5) & 15;
    int kt   = j >> 9;
    int g    = lane >> 2;
    int t4   = lane & 3;
    int e = et * 8 + g;
    int k = kt * 8 + t4;
    float w0 = __ldg(W + e * E_DIM + k);
    float w1 = __ldg(W + e * E_DIM + k + 4);
    unsigned h0 = tf32_of(w0), h1 = tf32_of(w1);
    float l0 = w0 - __uint_as_float(h0);
    float l1 = w1 - __uint_as_float(h1);
    g_wb[j] = make_uint4(h0, h1, __float_as_uint(l0), __float_as_uint(l1));
}

// ---------------------------------------------------------------------------
// Kernel 3b: combine: 4-plane reduction + normalization fused into staging,
// then split-tf32 GEMM, k-split across warp pairs (grid 1024).
// ---------------------------------------------------------------------------
__global__ __launch_bounds__(256) void combine_kernel(float* __restrict__ out) {
    __shared__ __align__(16) float sa[16 * 132];
    __shared__ float sred[4 * 32 * 4];

    int rb  = blockIdx.x >> 2;
    int eq  = blockIdx.x & 3;
    int row0 = rb * 16;
    int tid = threadIdx.x;
    int w   = tid >> 5;
    int lane = tid & 31;
    int g   = lane >> 2;
    int t4  = lane & 3;
    int et  = w & 3;
    int kh  = w >> 2;

#pragma unroll
    for (int j = 0; j < 2; j++) {
        int idx = tid + j * 256;
        int r  = idx >> 5;
        int c4 = idx & 31;
        int hh = c4 >> 1;
        float4 s = make_float4(0.f, 0.f, 0.f, 0.f);
        float l = 0.f;
#pragma unroll
        for (int ksp = 0; ksp < NSPLIT; ksp++) {
            float4 a = *reinterpret_cast<const float4*>(
                g_po + (size_t)ksp * NROWS_E * E_DIM + (size_t)row0 * E_DIM + idx * 4);
            s.x += a.x; s.y += a.y; s.z += a.z; s.w += a.w;
            l += g_pl[ksp * NROWS_E * 16 + (row0 + r) * 16 + hh];
        }
        float rinv = 1.0f / l;
        *reinterpret_cast<float4*>(sa + r * 132 + c4 * 4) =
            make_float4(s.x * rinv, s.y * rinv, s.z * rinv, s.w * rinv);
    }
    __syncthreads();

    float C0 = 0.f, C1 = 0.f, C2 = 0.f, C3 = 0.f;
    const float* sw = sa + g * 132;

#pragma unroll
    for (int kt = kh * 8; kt < kh * 8 + 8; kt++) {
        int kb = kt * 8;
        float a0 = sw[kb + t4];
        float a1 = sw[8 * 132 + kb + t4];
        float a2 = sw[kb + t4 + 4];
        float a3 = sw[8 * 132 + kb + t4 + 4];
        unsigned h0 = tf32_of(a0), h1 = tf32_of(a1), h2 = tf32_of(a2), h3 = tf32_of(a3);
        unsigned l0 = __float_as_uint(a0 - __uint_as_float(h0));
        unsigned l1 = __float_as_uint(a1 - __uint_as_float(h1));
        unsigned l2 = __float_as_uint(a2 - __uint_as_float(h2));
        unsigned l3 = __float_as_uint(a3 - __uint_as_float(h3));

        uint4 B = __ldg(&g_wb[(kt * 16 + eq * 4 + et) * 32 + lane]);
        mma8_acc(C0, C1, C2, C3, h0, h1, h2, h3, B.x, B.y);
        mma8_acc(C0, C1, C2, C3, h0, h1, h2, h3, B.z, B.w);
        mma8_acc(C0, C1, C2, C3, l0, l1, l2, l3, B.x, B.y);
    }

    if (kh == 1) {
        float* rp = sred + (et * 32 + lane) * 4;
        rp[0] = C0; rp[1] = C1; rp[2] = C2; rp[3] = C3;
    }
    __syncthreads();
    if (kh == 0) {
        const float* rp = sred + (et * 32 + lane) * 4;
        C0 += rp[0]; C1 += rp[1]; C2 += rp[2]; C3 += rp[3];
        int r_g = row0 + g;
        int e0  = eq * 32 + et * 8 + 2 * t4;
        *reinterpret_cast<float2*>(out + (size_t)r_g * E_DIM + e0) = make_float2(C0, C1);
        *reinterpret_cast<float2*>(out + (size_t)(r_g + 8) * E_DIM + e0) = make_float2(C2, C3);
    }
}

// ---------------------------------------------------------------------------
extern "C" void kernel_launch(void* const* d_in, const int* in_sizes, int n_in,
                              void* d_out, int out_size) {
    const float* x  = nullptr;
    const float* rx = nullptr;
    const float* cw = nullptr;
    for (int i = 0; i < n_in; i++) {
        if (in_sizes[i] == NROWS * DK)          x  = (const float*)d_in[i];
        else if (in_sizes[i] == DK)             rx = (const float*)d_in[i];
        else if (in_sizes[i] == E_DIM * E_DIM)  cw = (const float*)d_in[i];
    }
    if (!x)  x  = (const float*)d_in[0];
    if (!rx) rx = (const float*)d_in[1];
    if (!cw) cw = (const float*)d_in[2];

    float* out = (float*)d_out;

    // attn kept 4th — the launch slot ncu captures.
    pack_w<<<(16 * 16 * 32 + 255) / 256, 256>>>(cw);
    qkv_pack<<<NHEADS * (S_LEN / 2) / 256, 256>>>(x, rx);
    nop_kernel<<<1, 32>>>();
    attn_kernel<<<NHEADS * 32, 256>>>();
    combine_kernel<<<1024, 256>>>(out);
}

// round 17
// speedup vs baseline: 1.1260x; 1.1260x over previous
#include <cuda_runtime.h>
#include <cuda_bf16.h>
#include <cuda_fp16.h>
#include <math.h>

// ---------------------------------------------------------------------------
// QuantumAttention, analytic circuit collapse:
//   z_i = cos(x_i + p_i); proj[0] = z1..z7 ; proj[w>=1] = z0..zw
// pack_all (one launch): projections -> K/V fragment-order f16 + W split-tf32
// B-frags. attn: QK m16n8k8 f16-accum -> C-regs ARE PV A-frags, ex2.f16x2 in
// place, ones-mma denominators (round-15 loop, best measured). Split-K 2.
// combine: split-tf32 GEMM, 2-plane reduction + normalization in staging.
// 3 graph nodes total.
// ---------------------------------------------------------------------------

#define NROWS   65536
#define S_LEN   1024
#define NHEADS  64
#define DK      8
#define E_DIM   128
#define NROWS_E 4096
#define NSPLIT  2
#define KS_LEN  512          // keys per split block

__device__ float g_po[NSPLIT * NROWS_E * E_DIM];   // unnormalized O partials (4 MB)
__device__ float g_pl[NSPLIT * NROWS_E * 16];      // denominator partials (512 KB)
__device__ uint4 g_wb[16 * 16 * 32];               // W split B-fragments
__device__ unsigned g_k2[NHEADS * 4096];           // K f16x2, fragment order (1 MB)
__device__ unsigned g_v2[NHEADS * 4096];           // V f16x2, fragment order (1 MB)

__device__ __forceinline__ unsigned tf32_of(float f) {
    unsigned u; asm("cvt.rna.tf32.f32 %0, %1;" : "=r"(u) : "f"(f));
    return u;
}
__device__ __forceinline__ unsigned h2_of(float lo, float hi) {
    __half2 h = __floats2half2_rn(lo, hi);
    return *reinterpret_cast<unsigned*>(&h);
}
__device__ __forceinline__ unsigned ex2_h2(unsigned s) {
    unsigned d;
    asm("ex2.approx.f16x2 %0, %1;" : "=r"(d) : "r"(s));
    return d;
}
// f16 m16n8k8 with F16 accumulator: C packed as 2 f16x2 regs
__device__ __forceinline__ void mma8hh(unsigned& c01, unsigned& c23,
                                       unsigned a0, unsigned a1, unsigned b0) {
    asm("mma.sync.aligned.m16n8k8.row.col.f16.f16.f16.f16 "
        "{%0,%1},{%2,%3},{%4},{%5,%6};"
        : "=r"(c01), "=r"(c23)
        : "r"(a0), "r"(a1), "r"(b0), "r"(0u), "r"(0u));
}
// f16 m16n8k16, C(f32) += A*B
__device__ __forceinline__ void mma16h_acc(float& c0, float& c1, float& c2, float& c3,
                                           unsigned a0, unsigned a1, unsigned a2, unsigned a3,
                                           unsigned b0, unsigned b1) {
    asm("mma.sync.aligned.m16n8k16.row.col.f32.f16.f16.f32 "
        "{%0,%1,%2,%3},{%4,%5,%6,%7},{%8,%9},{%0,%1,%2,%3};"
        : "+f"(c0), "+f"(c1), "+f"(c2), "+f"(c3)
        : "r"(a0), "r"(a1), "r"(a2), "r"(a3), "r"(b0), "r"(b1));
}
// tf32 m16n8k8, C += A*B
__device__ __forceinline__ void mma8_acc(float& c0, float& c1, float& c2, float& c3,
                                         unsigned a0, unsigned a1, unsigned a2, unsigned a3,
                                         unsigned b0, unsigned b1) {
    asm("mma.sync.aligned.m16n8k8.row.col.f32.tf32.tf32.f32 "
        "{%0,%1,%2,%3},{%4,%5,%6,%7},{%8,%9},{%0,%1,%2,%3};"
        : "+f"(c0), "+f"(c1), "+f"(c2), "+f"(c3)
        : "r"(a0), "r"(a1), "r"(a2), "r"(a3), "r"(b0), "r"(b1));
}

__device__ __forceinline__ void proj8(float4 v0, float4 v1,
                                      const float* pv, float* o) {
    float z0 = __cosf(v0.x + pv[0]);
    float z1 = __cosf(v0.y + pv[1]);
    float z2 = __cosf(v0.z + pv[2]);
    float z3 = __cosf(v0.w + pv[3]);
    float z4 = __cosf(v1.x + pv[4]);
    float z5 = __cosf(v1.y + pv[5]);
    float z6 = __cosf(v1.z + pv[6]);
    float z7 = __cosf(v1.w + pv[7]);
    o[1] = z0 * z1;
    o[2] = o[1] * z2;
    o[3] = o[2] * z3;
    o[4] = o[3] * z4;
    o[5] = o[4] * z5;
    o[6] = o[5] * z6;
    o[7] = o[6] * z7;
    float t = z1 * z2;
    t *= z3; t *= z4; t *= z5; t *= z6; t *= z7;
    o[0] = t;
}

// fragment-order index for K word (row r, dim-slot t4) within a head
__device__ __forceinline__ int kidx(int r, int t4) {
    return (((r >> 5) * 8 + (r & 7)) << 4) + t4 * 4 + ((r & 31) >> 3);
}
// fragment-order index for V word (pair p, dim g)
__device__ __forceinline__ int vidx(int p, int g) {
    return (((p >> 4) * 8 + g) << 4) + (p & 3) * 4 + ((p & 15) >> 2);
}

// ---------------------------------------------------------------------------
// Kernel 1 (fused): blocks 0..127 = qkv projection+pack; 128..159 = W pack.
// ---------------------------------------------------------------------------
__global__ void pack_all(const float* __restrict__ x,
                         const float* __restrict__ rx,
                         const float* __restrict__ W) {
    int bx = blockIdx.x;
    int tid = threadIdx.x;

    if (bx < 128) {
        // ---- qkv: one key-pair per thread ----
        int r = bx * 256 + tid;
        int head = r >> 9;
        int j = r & 511;
        int bb = head >> 4;
        int hh = head & 15;

        float pv[8];
#pragma unroll
        for (int i = 0; i < 8; i++) pv[i] = __ldg(rx + i);

        const float4* x4 = reinterpret_cast<const float4*>(x);
        size_t r0 = ((size_t)((bb << 10) + 2 * j) << 4) + hh;
        float4 a0 = x4[r0 * 2];
        float4 a1 = x4[r0 * 2 + 1];
        float4 c0 = x4[(r0 + 16) * 2];
        float4 c1 = x4[(r0 + 16) * 2 + 1];

        float o[8], p[8];
        proj8(a0, a1, pv, o);
        proj8(c0, c1, pv, p);

        const float rs = 0.71421915f;   // sqrt(log2e / sqrt(8))
        unsigned* K = g_k2 + head * 4096;
        unsigned* V = g_v2 + head * 4096;

#pragma unroll
        for (int t4 = 0; t4 < 4; t4++) {
            K[kidx(2 * j,     t4)] = h2_of(o[2 * t4] * rs, o[2 * t4 + 1] * rs);
            K[kidx(2 * j + 1, t4)] = h2_of(p[2 * t4] * rs, p[2 * t4 + 1] * rs);
        }
#pragma unroll
        for (int g = 0; g < 8; g++) {
            V[vidx(j, g)] = h2_of(o[g], p[g]);
        }
    } else {
        // ---- W pack: split-tf32 B-fragments ----
        int j = (bx - 128) * 256 + tid;
        int lane = j & 31;
        int et   = (j >> 5) & 15;
        int kt   = j >> 9;
        int g    = lane >> 2;
        int t4   = lane & 3;
        int e = et * 8 + g;
        int k = kt * 8 + t4;
        float w0 = __ldg(W + e * E_DIM + k);
        float w1 = __ldg(W + e * E_DIM + k + 4);
        unsigned h0 = tf32_of(w0), h1 = tf32_of(w1);
        float l0 = w0 - __uint_as_float(h0);
        float l1 = w1 - __uint_as_float(h1);
        g_wb[j] = make_uint4(h0, h1, __float_as_uint(l0), __float_as_uint(l1));
    }
}

// ---------------------------------------------------------------------------
// Kernel 2: split-K(2) attention, round-15 loop (ones-mma denominators).
// bx: head = bx>>4, qt = (bx>>1)&7, ks = bx&1. 256 thr; 128 q x 512 keys.
// ---------------------------------------------------------------------------
__global__ __launch_bounds__(256, 5) void attn_kernel() {
    __shared__ __align__(16) unsigned sK2[2048];   // 8 KB
    __shared__ __align__(16) unsigned sV2[2048];   // 8 KB

    int bx   = blockIdx.x;
    int head = bx >> 4;
    int qt   = (bx >> 1) & 7;
    int ks   = bx & 1;
    int tid  = threadIdx.x;
    int w    = tid >> 5;
    int lane = tid & 31;
    int g    = lane >> 2;
    int t4   = lane & 3;

    const uint4* Ksrc = reinterpret_cast<const uint4*>(g_k2 + head * 4096 + ks * 2048);
    const uint4* Vsrc = reinterpret_cast<const uint4*>(g_v2 + head * 4096 + ks * 2048);
#pragma unroll
    for (int i = 0; i < 2; i++) {
        reinterpret_cast<uint4*>(sK2)[tid + i * 256] = Ksrc[tid + i * 256];
        reinterpret_cast<uint4*>(sV2)[tid + i * 256] = Vsrc[tid + i * 256];
    }
    __syncthreads();

    // Q A-frag: rows ar, ar+8 -> one LDG.64 (adjacent in fragment order)
    int ar = qt * 128 + w * 16 + g;
    const unsigned* Kg = g_k2 + head * 4096;
    uint2 Aq = *reinterpret_cast<const uint2*>(Kg + kidx(ar, t4));
    unsigned A0 = Aq.x, A1 = Aq.y;

    float Oa0 = 0.f, Oa1 = 0.f, Oa2 = 0.f, Oa3 = 0.f;
    float Ob0 = 0.f, Ob1 = 0.f, Ob2 = 0.f, Ob3 = 0.f;
    float La0 = 0.f, La1 = 0.f, La2 = 0.f, La3 = 0.f;
    float Lb0 = 0.f, Lb1 = 0.f, Lb2 = 0.f, Lb3 = 0.f;
    const unsigned BONE = 0x3C003C00u;

    int fo = g * 16 + t4 * 4;    // lane offset within a 128-word block

#pragma unroll 8
    for (int it = 0; it < KS_LEN / 32; it++) {
        uint4 kq = *reinterpret_cast<const uint4*>(sK2 + it * 128 + fo);
        uint4 vq = *reinterpret_cast<const uint4*>(sV2 + it * 128 + fo);

        unsigned s0, s1, t0, t1, u0, u1, v0, v1;
        mma8hh(s0, s1, A0, A1, kq.x);
        mma8hh(t0, t1, A0, A1, kq.y);
        mma8hh(u0, u1, A0, A1, kq.z);
        mma8hh(v0, v1, A0, A1, kq.w);

        unsigned pa01 = ex2_h2(s0);
        unsigned pa23 = ex2_h2(s1);
        unsigned ea01 = ex2_h2(t0);
        unsigned ea23 = ex2_h2(t1);
        unsigned pb01 = ex2_h2(u0);
        unsigned pb23 = ex2_h2(u1);
        unsigned eb01 = ex2_h2(v0);
        unsigned eb23 = ex2_h2(v1);

        mma16h_acc(Oa0, Oa1, Oa2, Oa3, pa01, pa23, ea01, ea23, vq.x, vq.y);
        mma16h_acc(Ob0, Ob1, Ob2, Ob3, pb01, pb23, eb01, eb23, vq.z, vq.w);
        mma16h_acc(La0, La1, La2, La3, pa01, pa23, ea01, ea23, BONE, BONE);
        mma16h_acc(Lb0, Lb1, Lb2, Lb3, pb01, pb23, eb01, eb23, BONE, BONE);
    }

    float O0 = Oa0 + Ob0, O1 = Oa1 + Ob1, O2 = Oa2 + Ob2, O3 = Oa3 + Ob3;

    int bb_ = head >> 4;
    int hh  = head & 15;
    int row = qt * 128 + w * 16 + g;
    int grow = (bb_ << 10) + row;
    size_t base = (size_t)ks * NROWS_E * E_DIM + (size_t)grow * E_DIM + hh * DK + 2 * t4;

    *reinterpret_cast<float2*>(g_po + base)              = make_float2(O0, O1);
    *reinterpret_cast<float2*>(g_po + base + 8 * E_DIM)  = make_float2(O2, O3);

    if (t4 == 0) {
        g_pl[ks * NROWS_E * 16 + grow * 16 + hh]       = La0 + Lb0;
        g_pl[ks * NROWS_E * 16 + (grow + 8) * 16 + hh] = La2 + Lb2;
    }
}

// ---------------------------------------------------------------------------
// Kernel 3: combine: 2-plane reduction + normalization fused into staging,
// then split-tf32 GEMM, k-split across warp pairs (grid 1024).
// ---------------------------------------------------------------------------
__global__ __launch_bounds__(256) void combine_kernel(float* __restrict__ out) {
    __shared__ __align__(16) float sa[16 * 132];
    __shared__ float sred[4 * 32 * 4];

    int rb  = blockIdx.x >> 2;
    int eq  = blockIdx.x & 3;
    int row0 = rb * 16;
    int tid = threadIdx.x;
    int w   = tid >> 5;
    int lane = tid & 31;
    int g   = lane >> 2;
    int t4  = lane & 3;
    int et  = w & 3;
    int kh  = w >> 2;

#pragma unroll
    for (int j = 0; j < 2; j++) {
        int idx = tid + j * 256;
        int r  = idx >> 5;
        int c4 = idx & 31;
        int hh = c4 >> 1;
        float4 s = make_float4(0.f, 0.f, 0.f, 0.f);
        float l = 0.f;
#pragma unroll
        for (int ksp = 0; ksp < NSPLIT; ksp++) {
            float4 a = *reinterpret_cast<const float4*>(
                g_po + (size_t)ksp * NROWS_E * E_DIM + (size_t)row0 * E_DIM + idx * 4);
            s.x += a.x; s.y += a.y; s.z += a.z; s.w += a.w;
            l += g_pl[ksp * NROWS_E * 16 + (row0 + r) * 16 + hh];
        }
        float rinv = 1.0f / l;
        *reinterpret_cast<float4*>(sa + r * 132 + c4 * 4) =
            make_float4(s.x * rinv, s.y * rinv, s.z * rinv, s.w * rinv);
    }
    __syncthreads();

    float C0 = 0.f, C1 = 0.f, C2 = 0.f, C3 = 0.f;
    const float* sw = sa + g * 132;

#pragma unroll
    for (int kt = kh * 8; kt < kh * 8 + 8; kt++) {
        int kb = kt * 8;
        float a0 = sw[kb + t4];
        float a1 = sw[8 * 132 + kb + t4];
        float a2 = sw[kb + t4 + 4];
        float a3 = sw[8 * 132 + kb + t4 + 4];
        unsigned h0 = tf32_of(a0), h1 = tf32_of(a1), h2 = tf32_of(a2), h3 = tf32_of(a3);
        unsigned l0 = __float_as_uint(a0 - __uint_as_float(h0));
        unsigned l1 = __float_as_uint(a1 - __uint_as_float(h1));
        unsigned l2 = __float_as_uint(a2 - __uint_as_float(h2));
        unsigned l3 = __float_as_uint(a3 - __uint_as_float(h3));

        uint4 B = __ldg(&g_wb[(kt * 16 + eq * 4 + et) * 32 + lane]);
        mma8_acc(C0, C1, C2, C3, h0, h1, h2, h3, B.x, B.y);
        mma8_acc(C0, C1, C2, C3, h0, h1, h2, h3, B.z, B.w);
        mma8_acc(C0, C1, C2, C3, l0, l1, l2, l3, B.x, B.y);
    }

    if (kh == 1) {
        float* rp = sred + (et * 32 + lane) * 4;
        rp[0] = C0; rp[1] = C1; rp[2] = C2; rp[3] = C3;
    }
    __syncthreads();
    if (kh == 0) {
        const float* rp = sred + (et * 32 + lane) * 4;
        C0 += rp[0]; C1 += rp[1]; C2 += rp[2]; C3 += rp[3];
        int r_g = row0 + g;
        int e0  = eq * 32 + et * 8 + 2 * t4;
        *reinterpret_cast<float2*>(out + (size_t)r_g * E_DIM + e0) = make_float2(C0, C1);
        *reinterpret_cast<float2*>(out + (size_t)(r_g + 8) * E_DIM + e0) = make_float2(C2, C3);
    }
}

// ---------------------------------------------------------------------------
extern "C" void kernel_launch(void* const* d_in, const int* in_sizes, int n_in,
                              void* d_out, int out_size) {
    const float* x  = nullptr;
    const float* rx = nullptr;
    const float* cw = nullptr;
    for (int i = 0; i < n_in; i++) {
        if (in_sizes[i] == NROWS * DK)          x  = (const float*)d_in[i];
        else if (in_sizes[i] == DK)             rx = (const float*)d_in[i];
        else if (in_sizes[i] == E_DIM * E_DIM)  cw = (const float*)d_in[i];
    }
    if (!x)  x  = (const float*)d_in[0];
    if (!rx) rx = (const float*)d_in[1];
    if (!cw) cw = (const float*)d_in[2];

    float* out = (float*)d_out;

    pack_all<<<160, 256>>>(x, rx, cw);
    attn_kernel<<<NHEADS * 16, 256>>>();
    combine_kernel<<<1024, 256>>>(out);
}